// round 7
// baseline (speedup 1.0000x reference)
#include <cuda_runtime.h>
#include <cuda_bf16.h>
#include <cstdint>

// Problem constants
#define MM   32
#define BB   1000
#define H1   512
#define H2   2048
#define DD   3072

#define X1_ROWS 2048   // rows 0..999 = h1, 1000..1999 = t1, 2000..2047 zero pad
#define T2_ROWS 1024   // rows 0..999 = t2, 1000..1023 zero pad
#define NPART   512

// ---------------------------------------------------------------------------
// Static device scratch (no allocation allowed anywhere).
// ---------------------------------------------------------------------------
__device__ __align__(16) __nv_bfloat16 g_X1hi[X1_ROWS * H1];   // 2 MB
__device__ __align__(16) __nv_bfloat16 g_X1lo[X1_ROWS * H1];   // 2 MB
__device__ __align__(16) __nv_bfloat16 g_W2thi[H2 * H1];       // 2 MB  [N=2048,K=512]
__device__ __align__(16) __nv_bfloat16 g_W2tlo[H2 * H1];       // 2 MB
__device__ __align__(16) __nv_bfloat16 g_W3thi[DD * H2];       // 12 MB [N=3072,K=2048]
__device__ __align__(16) __nv_bfloat16 g_W3tlo[DD * H2];       // 12 MB
__device__ __align__(16) __nv_bfloat16 g_T2hi[T2_ROWS * H2];   // 4 MB
__device__ __align__(16) __nv_bfloat16 g_T2lo[T2_ROWS * H2];   // 4 MB
__device__ float g_Y2[X1_ROWS * H2];                           // 16 MB fp32
__device__ float g_U3[T2_ROWS * DD];                           // 12 MB fp32
__device__ float g_part[NPART];

__device__ __forceinline__ uint32_t smem_u32(const void* p) {
    uint32_t a;
    asm("{ .reg .u64 t; cvta.to.shared.u64 t, %1; cvt.u32.u64 %0, t; }"
        : "=r"(a) : "l"(p));
    return a;
}

__device__ __forceinline__ void split_bf16(float x, __nv_bfloat16& hi, __nv_bfloat16& lo) {
    hi = __float2bfloat16_rn(x);
    lo = __float2bfloat16_rn(x - __bfloat162float(hi));
}

// ---------------------------------------------------------------------------
// K1: layer-1 forward + tangent -> bf16 hi/lo splits in g_X1hi/lo.
// ---------------------------------------------------------------------------
__global__ void k_layer1(const float* __restrict__ c0,
                         const float* __restrict__ c1,
                         const float* __restrict__ interior,
                         const float* __restrict__ W1,
                         const float* __restrict__ b1) {
    int b = blockIdx.x;            // 0..999
    __shared__ float zs[MM], ds[MM];
    if (threadIdx.x < MM) {
        int m = threadIdx.x;
        float zb = (b == 0)    ? c0[m] : interior[(b - 1) * MM + m];
        float cn = (b == BB-1) ? c1[m] : interior[b * MM + m];
        zs[m] = zb;
        ds[m] = cn - zb;
    }
    __syncthreads();
    for (int k = threadIdx.x; k < H1; k += blockDim.x) {
        float a = b1[k];
        float g = 0.0f;
        #pragma unroll
        for (int m = 0; m < MM; ++m) {
            float w = W1[m * H1 + k];
            a = fmaf(zs[m], w, a);
            g = fmaf(ds[m], w, g);
        }
        float h = fmaxf(a, 0.0f);
        float t = (a > 0.0f) ? g : 0.0f;
        __nv_bfloat16 hh, hl, th, tl;
        split_bf16(h, hh, hl);
        split_bf16(t, th, tl);
        g_X1hi[b * H1 + k]        = hh;
        g_X1lo[b * H1 + k]        = hl;
        g_X1hi[(BB + b) * H1 + k] = th;
        g_X1lo[(BB + b) * H1 + k] = tl;
    }
}

// Zero X1 pad rows 2000..2047 (d_out-style poison must not enter MMA tiles).
__global__ void k_zero_pad() {
    int i = blockIdx.x * blockDim.x + threadIdx.x;   // over 48*H1
    if (i < 48 * H1) {
        g_X1hi[2000 * H1 + i] = __float2bfloat16(0.0f);
        g_X1lo[2000 * H1 + i] = __float2bfloat16(0.0f);
    }
}

// ---------------------------------------------------------------------------
// Transpose + bf16-split:  W[K,N] fp32  ->  Thi/Tlo[N,K] bf16
// ---------------------------------------------------------------------------
__global__ void k_transpose_split(const float* __restrict__ W,
                                  __nv_bfloat16* __restrict__ Thi,
                                  __nv_bfloat16* __restrict__ Tlo,
                                  int K, int N) {
    __shared__ float tile[32][33];
    int n0 = blockIdx.x * 32;
    int k0 = blockIdx.y * 32;
    int tx = threadIdx.x, ty = threadIdx.y;
    #pragma unroll
    for (int r = 0; r < 32; r += 8)
        tile[ty + r][tx] = W[(size_t)(k0 + ty + r) * N + n0 + tx];
    __syncthreads();
    #pragma unroll
    for (int r = 0; r < 32; r += 8) {
        float x = tile[tx][ty + r];
        __nv_bfloat16 hi, lo;
        split_bf16(x, hi, lo);
        size_t o = (size_t)(n0 + ty + r) * K + k0 + tx;
        Thi[o] = hi;
        Tlo[o] = lo;
    }
}

// ---------------------------------------------------------------------------
// mma.sync bf16 GEMM with bf16x3 split folded in as effective K3 = 3K:
//   segment 0: Ahi * Bhi   segment 1: Ahi * Blo   segment 2: Alo * Bhi
// C[M,N] fp32 = sum.  A* are [M,K] bf16 K-major, B* are [N,K] bf16 K-major.
// CTA tile 128x128, BK=32, 256 threads, warp tile 32x64, cp.async double buffer.
// ---------------------------------------------------------------------------
#define BM 128
#define BN 128
#define BK 32
#define LDSR 40   // bf16 elems per smem row (80 bytes) -> conflict-free ldmatrix

__global__ void __launch_bounds__(256)
k_mma_gemm(const __nv_bfloat16* __restrict__ Ahi, const __nv_bfloat16* __restrict__ Alo,
           const __nv_bfloat16* __restrict__ Bhi, const __nv_bfloat16* __restrict__ Blo,
           float* __restrict__ C, int K, int N, int KT) {   // KT = 3K/BK
    __shared__ __nv_bfloat16 As[2][BM * LDSR];
    __shared__ __nv_bfloat16 Bs[2][BN * LDSR];

    const int tid  = threadIdx.x;
    const int lane = tid & 31;
    const int wid  = tid >> 5;
    const int wm   = wid >> 1;        // 0..3  (M direction, 32 rows each)
    const int wn   = wid & 1;         // 0..1  (N direction, 64 cols each)
    const int bCol = blockIdx.x * BN;
    const int bRow = blockIdx.y * BM;

    // Per-thread load slots: row = tid/2, two 16B chunks (8 bf16 each)
    const int ldRow = tid >> 1;
    const int ldC0  = (tid & 1) * 2;  // chunk pair base (0 or 2)

    const uint32_t asB[2] = { smem_u32(As[0]), smem_u32(As[1]) };
    const uint32_t bsB[2] = { smem_u32(Bs[0]), smem_u32(Bs[1]) };

    auto load_tile = [&](int kt, int buf) {
        int seg = (kt * BK) / K;                      // 0,1,2
        const __nv_bfloat16* Ag = (seg < 2)  ? Ahi : Alo;
        const __nv_bfloat16* Bg = (seg == 1) ? Blo : Bhi;
        int kb = kt * BK - seg * K;
        const __nv_bfloat16* aSrc = Ag + (size_t)(bRow + ldRow) * K + kb;
        const __nv_bfloat16* bSrc = Bg + (size_t)(bCol + ldRow) * K + kb;
        uint32_t aDst = asB[buf] + (uint32_t)(ldRow * LDSR * 2);
        uint32_t bDst = bsB[buf] + (uint32_t)(ldRow * LDSR * 2);
        #pragma unroll
        for (int c = ldC0; c < ldC0 + 2; ++c) {
            asm volatile("cp.async.cg.shared.global [%0], [%1], 16;"
                         :: "r"(aDst + c * 16), "l"(aSrc + c * 8) : "memory");
            asm volatile("cp.async.cg.shared.global [%0], [%1], 16;"
                         :: "r"(bDst + c * 16), "l"(bSrc + c * 8) : "memory");
        }
    };

    float acc[2][8][4];
    #pragma unroll
    for (int i = 0; i < 2; ++i)
        #pragma unroll
        for (int j = 0; j < 8; ++j)
            #pragma unroll
            for (int r = 0; r < 4; ++r) acc[i][j][r] = 0.0f;

    load_tile(0, 0);
    asm volatile("cp.async.commit_group;" ::: "memory");

    for (int kt = 0; kt < KT; ++kt) {
        const int buf = kt & 1;
        if (kt + 1 < KT) load_tile(kt + 1, buf ^ 1);
        asm volatile("cp.async.commit_group;" ::: "memory");
        asm volatile("cp.async.wait_group 1;" ::: "memory");
        __syncthreads();

        // ldmatrix lane address components (row-major, 80B row stride)
        const uint32_t lrow = (uint32_t)(lane & 15);
        const uint32_t lcol = (uint32_t)((lane >> 4) * 8);

        #pragma unroll
        for (int ks = 0; ks < BK; ks += 16) {
            uint32_t a[2][4];
            #pragma unroll
            for (int mf = 0; mf < 2; ++mf) {
                uint32_t addr = asB[buf] +
                    (uint32_t)(((wm * 32 + mf * 16) + lrow) * LDSR + ks + lcol) * 2;
                asm volatile("ldmatrix.sync.aligned.m8n8.x4.shared.b16 "
                             "{%0,%1,%2,%3}, [%4];"
                             : "=r"(a[mf][0]), "=r"(a[mf][1]),
                               "=r"(a[mf][2]), "=r"(a[mf][3]) : "r"(addr));
            }
            uint32_t b[4][4];
            #pragma unroll
            for (int g = 0; g < 4; ++g) {
                uint32_t addr = bsB[buf] +
                    (uint32_t)(((wn * 64 + g * 16) + lrow) * LDSR + ks + lcol) * 2;
                asm volatile("ldmatrix.sync.aligned.m8n8.x4.shared.b16 "
                             "{%0,%1,%2,%3}, [%4];"
                             : "=r"(b[g][0]), "=r"(b[g][1]),
                               "=r"(b[g][2]), "=r"(b[g][3]) : "r"(addr));
            }
            #pragma unroll
            for (int mf = 0; mf < 2; ++mf) {
                #pragma unroll
                for (int g = 0; g < 4; ++g) {
                    asm volatile(
                        "mma.sync.aligned.m16n8k16.row.col.f32.bf16.bf16.f32 "
                        "{%0,%1,%2,%3}, {%4,%5,%6,%7}, {%8,%9}, {%0,%1,%2,%3};"
                        : "+f"(acc[mf][2*g][0]), "+f"(acc[mf][2*g][1]),
                          "+f"(acc[mf][2*g][2]), "+f"(acc[mf][2*g][3])
                        : "r"(a[mf][0]), "r"(a[mf][1]), "r"(a[mf][2]), "r"(a[mf][3]),
                          "r"(b[g][0]), "r"(b[g][2]));
                    asm volatile(
                        "mma.sync.aligned.m16n8k16.row.col.f32.bf16.bf16.f32 "
                        "{%0,%1,%2,%3}, {%4,%5,%6,%7}, {%8,%9}, {%0,%1,%2,%3};"
                        : "+f"(acc[mf][2*g+1][0]), "+f"(acc[mf][2*g+1][1]),
                          "+f"(acc[mf][2*g+1][2]), "+f"(acc[mf][2*g+1][3])
                        : "r"(a[mf][0]), "r"(a[mf][1]), "r"(a[mf][2]), "r"(a[mf][3]),
                          "r"(b[g][1]), "r"(b[g][3]));
                }
            }
        }
        __syncthreads();
    }

    // Epilogue: direct fp32 stores (acc layout: rows l>>2 / +8, cols 2*(l&3))
    const int rBase = bRow + wm * 32 + (lane >> 2);
    const int cBase = bCol + wn * 64 + (lane & 3) * 2;
    #pragma unroll
    for (int mf = 0; mf < 2; ++mf) {
        #pragma unroll
        for (int nf = 0; nf < 8; ++nf) {
            int r = rBase + mf * 16;
            int c = cBase + nf * 8;
            *(float2*)&C[(size_t)r * N + c] =
                make_float2(acc[mf][nf][0], acc[mf][nf][1]);
            *(float2*)&C[(size_t)(r + 8) * N + c] =
                make_float2(acc[mf][nf][2], acc[mf][nf][3]);
        }
    }
}

// ---------------------------------------------------------------------------
// Layer-2 gate: t2 = (Y2[b]+b2 > 0) ? Y2[1000+b] : 0   -> bf16 hi/lo splits.
// ---------------------------------------------------------------------------
__global__ void k_relu_gate(const float* __restrict__ b2) {
    int idx = blockIdx.x * blockDim.x + threadIdx.x;
    if (idx >= T2_ROWS * H2) return;
    int b = idx >> 11;
    int j = idx & (H2 - 1);
    float v = 0.0f;
    if (b < BB) {
        float a = g_Y2[b * H2 + j] + b2[j];
        if (a > 0.0f) v = g_Y2[(BB + b) * H2 + j];
    }
    __nv_bfloat16 hi, lo;
    split_bf16(v, hi, lo);
    g_T2hi[idx] = hi;
    g_T2lo[idx] = lo;
}

// ---------------------------------------------------------------------------
// Deterministic two-stage sum of squares of U3.
// ---------------------------------------------------------------------------
__global__ void k_sqsum_partial() {
    const int n4 = (T2_ROWS * DD) / 4;
    const float4* u = (const float4*)g_U3;
    float s = 0.0f;
    for (int i = blockIdx.x * blockDim.x + threadIdx.x; i < n4;
         i += gridDim.x * blockDim.x) {
        float4 v = u[i];
        s += v.x * v.x + v.y * v.y + v.z * v.z + v.w * v.w;
    }
    __shared__ float red[256];
    red[threadIdx.x] = s;
    __syncthreads();
    for (int o = 128; o > 0; o >>= 1) {
        if (threadIdx.x < o) red[threadIdx.x] += red[threadIdx.x + o];
        __syncthreads();
    }
    if (threadIdx.x == 0) g_part[blockIdx.x] = red[0];
}

__global__ void k_finalize(float* __restrict__ out) {
    __shared__ float red[256];
    float s = 0.0f;
    for (int i = threadIdx.x; i < NPART; i += 256) s += g_part[i];
    red[threadIdx.x] = s;
    __syncthreads();
    for (int o = 128; o > 0; o >>= 1) {
        if (threadIdx.x < o) red[threadIdx.x] += red[threadIdx.x + o];
        __syncthreads();
    }
    if (threadIdx.x == 0) out[0] = red[0];
}

// ---------------------------------------------------------------------------
// Launch.  Inputs: 0:c0 1:c1 2:interior 3:W1 4:b1 5:W2 6:b2 7:W3 8:b3(unused)
// ---------------------------------------------------------------------------
extern "C" void kernel_launch(void* const* d_in, const int* in_sizes, int n_in,
                              void* d_out, int out_size) {
    const float* c0       = (const float*)d_in[0];
    const float* c1       = (const float*)d_in[1];
    const float* interior = (const float*)d_in[2];
    const float* W1       = (const float*)d_in[3];
    const float* b1       = (const float*)d_in[4];
    const float* W2       = (const float*)d_in[5];
    const float* b2       = (const float*)d_in[6];
    const float* W3       = (const float*)d_in[7];
    (void)in_sizes; (void)n_in; (void)out_size;

    __nv_bfloat16 *X1hi, *X1lo, *W2thi, *W2tlo, *W3thi, *W3tlo, *T2hi, *T2lo;
    float *Y2p, *U3p;
    cudaGetSymbolAddress((void**)&X1hi,  g_X1hi);
    cudaGetSymbolAddress((void**)&X1lo,  g_X1lo);
    cudaGetSymbolAddress((void**)&W2thi, g_W2thi);
    cudaGetSymbolAddress((void**)&W2tlo, g_W2tlo);
    cudaGetSymbolAddress((void**)&W3thi, g_W3thi);
    cudaGetSymbolAddress((void**)&W3tlo, g_W3tlo);
    cudaGetSymbolAddress((void**)&T2hi,  g_T2hi);
    cudaGetSymbolAddress((void**)&T2lo,  g_T2lo);
    cudaGetSymbolAddress((void**)&Y2p,   g_Y2);
    cudaGetSymbolAddress((void**)&U3p,   g_U3);

    // Weight transpose+split
    k_transpose_split<<<dim3(H2 / 32, H1 / 32), dim3(32, 8)>>>(W2, W2thi, W2tlo, H1, H2);
    k_transpose_split<<<dim3(DD / 32, H2 / 32), dim3(32, 8)>>>(W3, W3thi, W3tlo, H2, DD);

    // L1 forward + tangent, pad zeroing
    k_layer1<<<BB, 256>>>(c0, c1, interior, W1, b1);
    k_zero_pad<<<(48 * H1 + 255) / 256, 256>>>();

    // GEMM1: [h1;t1](2048x512) @ W2 -> Y2 (2048x2048), K3 = 1536
    k_mma_gemm<<<dim3(H2 / BN, X1_ROWS / BM), 256>>>(
        X1hi, X1lo, W2thi, W2tlo, Y2p, H1, H2, 3 * H1 / BK);

    // gate -> bf16 splits
    k_relu_gate<<<(T2_ROWS * H2 + 255) / 256, 256>>>(b2);

    // GEMM2: t2(1024x2048) @ W3 -> U3 (1024x3072), K3 = 6144
    k_mma_gemm<<<dim3(DD / BN, T2_ROWS / BM), 256>>>(
        T2hi, T2lo, W3thi, W3tlo, U3p, H2, DD, 3 * H2 / BK);

    // energy = sum(U3^2)
    k_sqsum_partial<<<NPART, 256>>>();
    k_finalize<<<1, 256>>>((float*)d_out);
}

// round 8
// speedup vs baseline: 1.1549x; 1.1549x over previous
#include <cuda_runtime.h>
#include <cuda_bf16.h>
#include <cstdint>

// Problem constants
#define MM   32
#define BB   1000
#define H1   512
#define H2   2048
#define DD   3072

#define X1_ROWS 2048   // interleaved: row 2b = h_b, row 2b+1 = t_b (b<1024, pads 0)
#define T2_ROWS 1024   // rows 0..999 = t2, 1000..1023 zero
#define NPART   512

// ---------------------------------------------------------------------------
// Static device scratch.
// ---------------------------------------------------------------------------
__device__ __align__(16) __nv_bfloat16 g_X1hi[X1_ROWS * H1];   // 2 MB
__device__ __align__(16) __nv_bfloat16 g_X1lo[X1_ROWS * H1];   // 2 MB
__device__ __align__(16) __nv_bfloat16 g_W2thi[H2 * H1];       // [N=2048,K=512]
__device__ __align__(16) __nv_bfloat16 g_W2tlo[H2 * H1];
__device__ __align__(16) __nv_bfloat16 g_W3thi[DD * H2];       // [N=3072,K=2048]
__device__ __align__(16) __nv_bfloat16 g_W3tlo[DD * H2];
__device__ __align__(16) __nv_bfloat16 g_T2hi[T2_ROWS * H2];
__device__ __align__(16) __nv_bfloat16 g_T2lo[T2_ROWS * H2];
__device__ float g_part[NPART];

__device__ __forceinline__ uint32_t smem_u32(const void* p) {
    uint32_t a;
    asm("{ .reg .u64 t; cvta.to.shared.u64 t, %1; cvt.u32.u64 %0, t; }"
        : "=r"(a) : "l"(p));
    return a;
}
__device__ __forceinline__ void split_bf16(float x, __nv_bfloat16& hi, __nv_bfloat16& lo) {
    hi = __float2bfloat16_rn(x);
    lo = __float2bfloat16_rn(x - __bfloat162float(hi));
}

// ---------------------------------------------------------------------------
// K1: layer-1 forward + tangent -> interleaved bf16 hi/lo rows (2b, 2b+1).
// Blocks 1000..1023 write zero pad pairs.
// ---------------------------------------------------------------------------
__global__ void k_layer1(const float* __restrict__ c0,
                         const float* __restrict__ c1,
                         const float* __restrict__ interior,
                         const float* __restrict__ W1,
                         const float* __restrict__ b1) {
    int b = blockIdx.x;            // 0..1023
    if (b >= BB) {
        const __nv_bfloat16 z = __float2bfloat16(0.0f);
        for (int k = threadIdx.x; k < H1; k += blockDim.x) {
            g_X1hi[(2 * b) * H1 + k]     = z;
            g_X1lo[(2 * b) * H1 + k]     = z;
            g_X1hi[(2 * b + 1) * H1 + k] = z;
            g_X1lo[(2 * b + 1) * H1 + k] = z;
        }
        return;
    }
    __shared__ float zs[MM], ds[MM];
    if (threadIdx.x < MM) {
        int m = threadIdx.x;
        float zb = (b == 0)    ? c0[m] : interior[(b - 1) * MM + m];
        float cn = (b == BB-1) ? c1[m] : interior[b * MM + m];
        zs[m] = zb;
        ds[m] = cn - zb;
    }
    __syncthreads();
    for (int k = threadIdx.x; k < H1; k += blockDim.x) {
        float a = b1[k];
        float g = 0.0f;
        #pragma unroll
        for (int m = 0; m < MM; ++m) {
            float w = W1[m * H1 + k];
            a = fmaf(zs[m], w, a);
            g = fmaf(ds[m], w, g);
        }
        float h = fmaxf(a, 0.0f);
        float t = (a > 0.0f) ? g : 0.0f;
        __nv_bfloat16 hh, hl, th, tl;
        split_bf16(h, hh, hl);
        split_bf16(t, th, tl);
        g_X1hi[(2 * b) * H1 + k]     = hh;   // even row = h
        g_X1lo[(2 * b) * H1 + k]     = hl;
        g_X1hi[(2 * b + 1) * H1 + k] = th;   // odd row = t
        g_X1lo[(2 * b + 1) * H1 + k] = tl;
    }
}

// ---------------------------------------------------------------------------
// Transpose + bf16-split:  W[K,N] fp32  ->  Thi/Tlo[N,K] bf16
// ---------------------------------------------------------------------------
__global__ void k_transpose_split(const float* __restrict__ W,
                                  __nv_bfloat16* __restrict__ Thi,
                                  __nv_bfloat16* __restrict__ Tlo,
                                  int K, int N) {
    __shared__ float tile[32][33];
    int n0 = blockIdx.x * 32;
    int k0 = blockIdx.y * 32;
    int tx = threadIdx.x, ty = threadIdx.y;
    #pragma unroll
    for (int r = 0; r < 32; r += 8)
        tile[ty + r][tx] = W[(size_t)(k0 + ty + r) * N + n0 + tx];
    __syncthreads();
    #pragma unroll
    for (int r = 0; r < 32; r += 8) {
        float x = tile[tx][ty + r];
        __nv_bfloat16 hi, lo;
        split_bf16(x, hi, lo);
        size_t o = (size_t)(n0 + ty + r) * K + k0 + tx;
        Thi[o] = hi;
        Tlo[o] = lo;
    }
}

// ---------------------------------------------------------------------------
// mma.sync bf16 GEMM, bf16x3 split folded as K3 = 3K, 4-stage cp.async.
// MODE 0: GEMM1 — fused ReLU-gate epilogue writing g_T2hi/lo (uses b2, aux).
// MODE 1: GEMM2 — fused sum-of-squares epilogue writing g_part[cta].
// ---------------------------------------------------------------------------
#define BM 128
#define BN 128
#define BK 32
#define LDSR 40          // bf16 per smem row (80B) -> conflict-free ldmatrix
#define STAGES 4
#define TILE_E (BM * LDSR)                 // elems per A (or B) stage
#define SMEM_BYTES (2 * STAGES * TILE_E * 2)

template <int MODE>
__global__ void __launch_bounds__(256, 2)
k_mma_gemm(const __nv_bfloat16* __restrict__ Ahi, const __nv_bfloat16* __restrict__ Alo,
           const __nv_bfloat16* __restrict__ Bhi, const __nv_bfloat16* __restrict__ Blo,
           const float* __restrict__ aux,   // MODE0: b2;  MODE1: unused
           int K, int N, int KT) {          // KT = 3K/BK
    extern __shared__ __nv_bfloat16 sm[];
    __nv_bfloat16* As = sm;                       // STAGES * TILE_E
    __nv_bfloat16* Bs = sm + STAGES * TILE_E;

    const int tid  = threadIdx.x;
    const int lane = tid & 31;
    const int wid  = tid >> 5;
    const int wm   = wid >> 1;        // 0..3
    const int wn   = wid & 1;         // 0..1
    const int bCol = blockIdx.x * BN;
    const int bRow = blockIdx.y * BM;

    const int ldRow = tid >> 1;
    const int ldC0  = (tid & 1) * 2;

    uint32_t asB[STAGES], bsB[STAGES];
    #pragma unroll
    for (int s = 0; s < STAGES; ++s) {
        asB[s] = smem_u32(As + s * TILE_E);
        bsB[s] = smem_u32(Bs + s * TILE_E);
    }

    auto load_tile = [&](int kt, int buf) {
        int seg = (kt * BK) / K;                      // 0,1,2
        const __nv_bfloat16* Ag = (seg < 2)  ? Ahi : Alo;
        const __nv_bfloat16* Bg = (seg == 1) ? Blo : Bhi;
        int kb = kt * BK - seg * K;
        const __nv_bfloat16* aSrc = Ag + (size_t)(bRow + ldRow) * K + kb;
        const __nv_bfloat16* bSrc = Bg + (size_t)(bCol + ldRow) * K + kb;
        uint32_t aDst = asB[buf] + (uint32_t)(ldRow * LDSR * 2);
        uint32_t bDst = bsB[buf] + (uint32_t)(ldRow * LDSR * 2);
        #pragma unroll
        for (int c = ldC0; c < ldC0 + 2; ++c) {
            asm volatile("cp.async.cg.shared.global [%0], [%1], 16;"
                         :: "r"(aDst + c * 16), "l"(aSrc + c * 8) : "memory");
            asm volatile("cp.async.cg.shared.global [%0], [%1], 16;"
                         :: "r"(bDst + c * 16), "l"(bSrc + c * 8) : "memory");
        }
    };

    float acc[2][8][4];
    #pragma unroll
    for (int i = 0; i < 2; ++i)
        #pragma unroll
        for (int j = 0; j < 8; ++j)
            #pragma unroll
            for (int r = 0; r < 4; ++r) acc[i][j][r] = 0.0f;

    // Prologue: fill 3 stages
    #pragma unroll
    for (int s = 0; s < STAGES - 1; ++s) {
        load_tile(s, s);
        asm volatile("cp.async.commit_group;" ::: "memory");
    }

    const uint32_t lrow = (uint32_t)(lane & 15);
    const uint32_t lcol = (uint32_t)((lane >> 4) * 8);

    for (int kt = 0; kt < KT; ++kt) {
        asm volatile("cp.async.wait_group %0;" :: "n"(STAGES - 2) : "memory");
        __syncthreads();
        // Issue next load AFTER the barrier (buffer (kt+3)%4 was read at kt-1).
        if (kt + STAGES - 1 < KT) load_tile(kt + STAGES - 1, (kt + STAGES - 1) & 3);
        asm volatile("cp.async.commit_group;" ::: "memory");

        const int buf = kt & 3;
        #pragma unroll
        for (int ks = 0; ks < BK; ks += 16) {
            uint32_t a[2][4];
            #pragma unroll
            for (int mf = 0; mf < 2; ++mf) {
                uint32_t addr = asB[buf] +
                    (uint32_t)(((wm * 32 + mf * 16) + lrow) * LDSR + ks + lcol) * 2;
                asm volatile("ldmatrix.sync.aligned.m8n8.x4.shared.b16 "
                             "{%0,%1,%2,%3}, [%4];"
                             : "=r"(a[mf][0]), "=r"(a[mf][1]),
                               "=r"(a[mf][2]), "=r"(a[mf][3]) : "r"(addr));
            }
            uint32_t b[4][4];
            #pragma unroll
            for (int g = 0; g < 4; ++g) {
                uint32_t addr = bsB[buf] +
                    (uint32_t)(((wn * 64 + g * 16) + lrow) * LDSR + ks + lcol) * 2;
                asm volatile("ldmatrix.sync.aligned.m8n8.x4.shared.b16 "
                             "{%0,%1,%2,%3}, [%4];"
                             : "=r"(b[g][0]), "=r"(b[g][1]),
                               "=r"(b[g][2]), "=r"(b[g][3]) : "r"(addr));
            }
            #pragma unroll
            for (int mf = 0; mf < 2; ++mf) {
                #pragma unroll
                for (int g = 0; g < 4; ++g) {
                    asm volatile(
                        "mma.sync.aligned.m16n8k16.row.col.f32.bf16.bf16.f32 "
                        "{%0,%1,%2,%3}, {%4,%5,%6,%7}, {%8,%9}, {%0,%1,%2,%3};"
                        : "+f"(acc[mf][2*g][0]), "+f"(acc[mf][2*g][1]),
                          "+f"(acc[mf][2*g][2]), "+f"(acc[mf][2*g][3])
                        : "r"(a[mf][0]), "r"(a[mf][1]), "r"(a[mf][2]), "r"(a[mf][3]),
                          "r"(b[g][0]), "r"(b[g][2]));
                    asm volatile(
                        "mma.sync.aligned.m16n8k16.row.col.f32.bf16.bf16.f32 "
                        "{%0,%1,%2,%3}, {%4,%5,%6,%7}, {%8,%9}, {%0,%1,%2,%3};"
                        : "+f"(acc[mf][2*g+1][0]), "+f"(acc[mf][2*g+1][1]),
                          "+f"(acc[mf][2*g+1][2]), "+f"(acc[mf][2*g+1][3])
                        : "r"(a[mf][0]), "r"(a[mf][1]), "r"(a[mf][2]), "r"(a[mf][3]),
                          "r"(b[g][1]), "r"(b[g][3]));
                }
            }
        }
    }

    if (MODE == 0) {
        // Fused gate epilogue. Row r = bRow + wm*32 + mf*16 + half*8 + (lane>>2).
        // Even rows = a2-source (u2_fwd), odd rows = u2_tangent. shfl_xor(4)
        // pairs row 2b (q even) with row 2b+1 (q odd).
        const int q    = lane >> 2;
        const bool odd = (q & 1) != 0;
        const int cB   = bCol + wn * 64 + (lane & 3) * 2;
        #pragma unroll
        for (int nf = 0; nf < 8; ++nf) {
            const int c = cB + nf * 8;
            const float2 b2v = *(const float2*)&aux[c];
            #pragma unroll
            for (int mf = 0; mf < 2; ++mf) {
                #pragma unroll
                for (int half = 0; half < 2; ++half) {
                    float x = acc[mf][nf][half * 2 + 0];
                    float y = acc[mf][nf][half * 2 + 1];
                    // flags from this thread's values (valid on even-row threads)
                    int fl = ((x + b2v.x) > 0.0f ? 1 : 0) |
                             ((y + b2v.y) > 0.0f ? 2 : 0);
                    int pf = __shfl_xor_sync(0xFFFFFFFFu, fl, 4);
                    if (odd) {
                        int r = bRow + wm * 32 + mf * 16 + half * 8 + q; // odd
                        int tb = r >> 1;                                  // t2 row
                        float tx = (pf & 1) ? x : 0.0f;
                        float ty = (pf & 2) ? y : 0.0f;
                        __nv_bfloat16 hx, lx, hy, ly;
                        split_bf16(tx, hx, lx);
                        split_bf16(ty, hy, ly);
                        __nv_bfloat162 h2; h2.x = hx; h2.y = hy;
                        __nv_bfloat162 l2; l2.x = lx; l2.y = ly;
                        *(__nv_bfloat162*)&g_T2hi[(size_t)tb * H2 + c] = h2;
                        *(__nv_bfloat162*)&g_T2lo[(size_t)tb * H2 + c] = l2;
                    }
                }
            }
        }
    } else {
        // Fused sum-of-squares epilogue (deterministic).
        float s = 0.0f;
        #pragma unroll
        for (int mf = 0; mf < 2; ++mf)
            #pragma unroll
            for (int nf = 0; nf < 8; ++nf)
                #pragma unroll
                for (int r = 0; r < 4; ++r) {
                    float v = acc[mf][nf][r];
                    s = fmaf(v, v, s);
                }
        #pragma unroll
        for (int o = 16; o > 0; o >>= 1)
            s += __shfl_xor_sync(0xFFFFFFFFu, s, o);
        __syncthreads();                       // smem buffers no longer needed
        float* red = (float*)sm;
        if (lane == 0) red[wid] = s;
        __syncthreads();
        if (tid == 0) {
            float tot = 0.0f;
            #pragma unroll
            for (int w = 0; w < 8; ++w) tot += red[w];
            g_part[blockIdx.y * gridDim.x + blockIdx.x] = tot;
        }
    }
}

// ---------------------------------------------------------------------------
// Final deterministic sum over n partials.
// ---------------------------------------------------------------------------
__global__ void k_finalize(float* __restrict__ out, int n) {
    __shared__ float red[256];
    float s = 0.0f;
    for (int i = threadIdx.x; i < n; i += 256) s += g_part[i];
    red[threadIdx.x] = s;
    __syncthreads();
    for (int o = 128; o > 0; o >>= 1) {
        if (threadIdx.x < o) red[threadIdx.x] += red[threadIdx.x + o];
        __syncthreads();
    }
    if (threadIdx.x == 0) out[0] = red[0];
}

// ---------------------------------------------------------------------------
// Launch.  Inputs: 0:c0 1:c1 2:interior 3:W1 4:b1 5:W2 6:b2 7:W3 8:b3(unused)
// ---------------------------------------------------------------------------
extern "C" void kernel_launch(void* const* d_in, const int* in_sizes, int n_in,
                              void* d_out, int out_size) {
    const float* c0       = (const float*)d_in[0];
    const float* c1       = (const float*)d_in[1];
    const float* interior = (const float*)d_in[2];
    const float* W1       = (const float*)d_in[3];
    const float* b1       = (const float*)d_in[4];
    const float* W2       = (const float*)d_in[5];
    const float* b2       = (const float*)d_in[6];
    const float* W3       = (const float*)d_in[7];
    (void)in_sizes; (void)n_in; (void)out_size;

    __nv_bfloat16 *X1hi, *X1lo, *W2thi, *W2tlo, *W3thi, *W3tlo, *T2hi, *T2lo;
    cudaGetSymbolAddress((void**)&X1hi,  g_X1hi);
    cudaGetSymbolAddress((void**)&X1lo,  g_X1lo);
    cudaGetSymbolAddress((void**)&W2thi, g_W2thi);
    cudaGetSymbolAddress((void**)&W2tlo, g_W2tlo);
    cudaGetSymbolAddress((void**)&W3thi, g_W3thi);
    cudaGetSymbolAddress((void**)&W3tlo, g_W3tlo);
    cudaGetSymbolAddress((void**)&T2hi,  g_T2hi);
    cudaGetSymbolAddress((void**)&T2lo,  g_T2lo);

    cudaFuncSetAttribute(k_mma_gemm<0>,
                         cudaFuncAttributeMaxDynamicSharedMemorySize, SMEM_BYTES);
    cudaFuncSetAttribute(k_mma_gemm<1>,
                         cudaFuncAttributeMaxDynamicSharedMemorySize, SMEM_BYTES);

    // Weight transpose+split
    k_transpose_split<<<dim3(H2 / 32, H1 / 32), dim3(32, 8)>>>(W2, W2thi, W2tlo, H1, H2);
    k_transpose_split<<<dim3(DD / 32, H2 / 32), dim3(32, 8)>>>(W3, W3thi, W3tlo, H2, DD);

    // L1 forward + tangent (interleaved rows, pads zeroed in-kernel)
    k_layer1<<<1024, 256>>>(c0, c1, interior, W1, b1);

    // GEMM1 + fused gate: X1(2048x512) @ W2t -> t2 bf16 splits
    k_mma_gemm<0><<<dim3(H2 / BN, X1_ROWS / BM), 256, SMEM_BYTES>>>(
        X1hi, X1lo, W2thi, W2tlo, b2, H1, H2, 3 * H1 / BK);

    // GEMM2 + fused sqsum: t2(1024x2048) @ W3t -> per-CTA partials
    const int g2x = DD / BN, g2y = T2_ROWS / BM;   // 24 x 8 = 192
    k_mma_gemm<1><<<dim3(g2x, g2y), 256, SMEM_BYTES>>>(
        T2hi, T2lo, W3thi, W3tlo, nullptr, H2, DD, 3 * H2 / BK);

    // energy = sum of partials (fixed order)
    k_finalize<<<1, 256>>>((float*)d_out, g2x * g2y);
}

// round 9
// speedup vs baseline: 1.1839x; 1.0251x over previous
#include <cuda_runtime.h>
#include <cuda_bf16.h>
#include <cstdint>

// Problem constants
#define MM   32
#define BB   1000
#define H1   512
#define H2   2048
#define DD   3072

#define X1_ROWS 2048   // interleaved: row 2b = h_b, row 2b+1 = t_b (b<1024, pads 0)
#define T2_ROWS 1024
#define NPART   512

// ---------------------------------------------------------------------------
// Static device scratch.
// ---------------------------------------------------------------------------
__device__ __align__(16) __nv_bfloat16 g_X1hi[X1_ROWS * H1];
__device__ __align__(16) __nv_bfloat16 g_X1lo[X1_ROWS * H1];
__device__ __align__(16) __nv_bfloat16 g_W2thi[H2 * H1];       // [N=2048,K=512]
__device__ __align__(16) __nv_bfloat16 g_W2tlo[H2 * H1];
__device__ __align__(16) __nv_bfloat16 g_W3thi[DD * H2];       // [N=3072,K=2048]
__device__ __align__(16) __nv_bfloat16 g_W3tlo[DD * H2];
__device__ __align__(16) __nv_bfloat16 g_T2hi[T2_ROWS * H2];
__device__ __align__(16) __nv_bfloat16 g_T2lo[T2_ROWS * H2];
__device__ float g_part[NPART];

__device__ __forceinline__ uint32_t smem_u32(const void* p) {
    uint32_t a;
    asm("{ .reg .u64 t; cvta.to.shared.u64 t, %1; cvt.u32.u64 %0, t; }"
        : "=r"(a) : "l"(p));
    return a;
}
__device__ __forceinline__ void split_bf16(float x, __nv_bfloat16& hi, __nv_bfloat16& lo) {
    hi = __float2bfloat16_rn(x);
    lo = __float2bfloat16_rn(x - __bfloat162float(hi));
}

// ---------------------------------------------------------------------------
// K1: layer-1 forward + tangent -> interleaved bf16 hi/lo rows (2b, 2b+1).
// ---------------------------------------------------------------------------
__global__ void k_layer1(const float* __restrict__ c0,
                         const float* __restrict__ c1,
                         const float* __restrict__ interior,
                         const float* __restrict__ W1,
                         const float* __restrict__ b1) {
    int b = blockIdx.x;            // 0..1023
    if (b >= BB) {
        const __nv_bfloat16 z = __float2bfloat16(0.0f);
        for (int k = threadIdx.x; k < H1; k += blockDim.x) {
            g_X1hi[(2 * b) * H1 + k]     = z;
            g_X1lo[(2 * b) * H1 + k]     = z;
            g_X1hi[(2 * b + 1) * H1 + k] = z;
            g_X1lo[(2 * b + 1) * H1 + k] = z;
        }
        return;
    }
    __shared__ float zs[MM], ds[MM];
    if (threadIdx.x < MM) {
        int m = threadIdx.x;
        float zb = (b == 0)    ? c0[m] : interior[(b - 1) * MM + m];
        float cn = (b == BB-1) ? c1[m] : interior[b * MM + m];
        zs[m] = zb;
        ds[m] = cn - zb;
    }
    __syncthreads();
    for (int k = threadIdx.x; k < H1; k += blockDim.x) {
        float a = b1[k];
        float g = 0.0f;
        #pragma unroll
        for (int m = 0; m < MM; ++m) {
            float w = W1[m * H1 + k];
            a = fmaf(zs[m], w, a);
            g = fmaf(ds[m], w, g);
        }
        float h = fmaxf(a, 0.0f);
        float t = (a > 0.0f) ? g : 0.0f;
        __nv_bfloat16 hh, hl, th, tl;
        split_bf16(h, hh, hl);
        split_bf16(t, th, tl);
        g_X1hi[(2 * b) * H1 + k]     = hh;
        g_X1lo[(2 * b) * H1 + k]     = hl;
        g_X1hi[(2 * b + 1) * H1 + k] = th;
        g_X1lo[(2 * b + 1) * H1 + k] = tl;
    }
}

// ---------------------------------------------------------------------------
// Transpose + bf16-split:  W[K,N] fp32  ->  Thi/Tlo[N,K] bf16
// ---------------------------------------------------------------------------
__global__ void k_transpose_split(const float* __restrict__ W,
                                  __nv_bfloat16* __restrict__ Thi,
                                  __nv_bfloat16* __restrict__ Tlo,
                                  int K, int N) {
    __shared__ float tile[32][33];
    int n0 = blockIdx.x * 32;
    int k0 = blockIdx.y * 32;
    int tx = threadIdx.x, ty = threadIdx.y;
    #pragma unroll
    for (int r = 0; r < 32; r += 8)
        tile[ty + r][tx] = W[(size_t)(k0 + ty + r) * N + n0 + tx];
    __syncthreads();
    #pragma unroll
    for (int r = 0; r < 32; r += 8) {
        float x = tile[tx][ty + r];
        __nv_bfloat16 hi, lo;
        split_bf16(x, hi, lo);
        size_t o = (size_t)(n0 + ty + r) * K + k0 + tx;
        Thi[o] = hi;
        Tlo[o] = lo;
    }
}

// ---------------------------------------------------------------------------
// mma.sync bf16 GEMM, bf16x3 split folded as K3 = 3K, 5-stage cp.async,
// fragment-level software pipeline.
// MODE 0: GEMM1 — fused ReLU-gate epilogue -> g_T2hi/lo (aux = b2).
// MODE 1: GEMM2 — fused sum-of-squares epilogue -> g_part[cta].
// ---------------------------------------------------------------------------
#define BM 128
#define BN 128
#define BK 32
#define LDSR 40                     // bf16/row (80 B) -> conflict-free ldmatrix
#define STAGES 5
#define TILE_B (BM * LDSR * 2)      // 10240 bytes per operand stage
#define SMEM_BYTES (2 * STAGES * TILE_B)   // 102400

#define LDSM_X4(d, addr)                                                     \
    asm volatile("ldmatrix.sync.aligned.m8n8.x4.shared.b16 {%0,%1,%2,%3}, [%4];" \
                 : "=r"((d)[0]), "=r"((d)[1]), "=r"((d)[2]), "=r"((d)[3])    \
                 : "r"(addr))

#define MMA_16816(ac, av, r0, r1)                                            \
    asm volatile(                                                            \
        "mma.sync.aligned.m16n8k16.row.col.f32.bf16.bf16.f32 "               \
        "{%0,%1,%2,%3}, {%4,%5,%6,%7}, {%8,%9}, {%0,%1,%2,%3};"              \
        : "+f"((ac)[0]), "+f"((ac)[1]), "+f"((ac)[2]), "+f"((ac)[3])         \
        : "r"((av)[0]), "r"((av)[1]), "r"((av)[2]), "r"((av)[3]),            \
          "r"(r0), "r"(r1))

template <int MODE>
__global__ void __launch_bounds__(256, 2)
k_mma_gemm(const __nv_bfloat16* __restrict__ Ahi, const __nv_bfloat16* __restrict__ Alo,
           const __nv_bfloat16* __restrict__ Bhi, const __nv_bfloat16* __restrict__ Blo,
           const float* __restrict__ aux,
           int K, int N, int KT) {          // KT = 3K/BK
    extern __shared__ char sm[];
    const uint32_t aBase = smem_u32(sm);
    const uint32_t bBase = aBase + STAGES * TILE_B;
    const uint32_t aEnd  = bBase;
    const uint32_t bEnd  = bBase + STAGES * TILE_B;

    const int tid  = threadIdx.x;
    const int lane = tid & 31;
    const int wid  = tid >> 5;
    const int wm   = wid >> 1;        // 0..3
    const int wn   = wid & 1;         // 0..1
    const int bCol = blockIdx.x * BN;
    const int bRow = blockIdx.y * BM;

    const int ldRow = tid >> 1;
    const int ldC0  = (tid & 1) * 2;

    // per-warp/lane ldmatrix byte offsets within a stage
    const uint32_t lrow = (uint32_t)(lane & 15);
    const uint32_t lcol = (uint32_t)((lane >> 4) * 8);
    const uint32_t aOff0 = ((wm * 32 +  0 + lrow) * LDSR + lcol) * 2;
    const uint32_t aOff1 = ((wm * 32 + 16 + lrow) * LDSR + lcol) * 2;
    uint32_t bOff[4];
    #pragma unroll
    for (int g = 0; g < 4; ++g)
        bOff[g] = ((wn * 64 + g * 16 + lrow) * LDSR + lcol) * 2;
    // per-thread cp.async store offsets within a stage
    const uint32_t stOff = (uint32_t)(ldRow * (LDSR * 2) + ldC0 * 16);

    auto load_tile = [&](int kt, uint32_t aDst, uint32_t bDst) {
        int seg = (kt * BK) / K;                      // 0,1,2
        const __nv_bfloat16* Ag = (seg < 2)  ? Ahi : Alo;
        const __nv_bfloat16* Bg = (seg == 1) ? Blo : Bhi;
        int kb = kt * BK - seg * K;
        const __nv_bfloat16* aSrc = Ag + (size_t)(bRow + ldRow) * K + kb + ldC0 * 8;
        const __nv_bfloat16* bSrc = Bg + (size_t)(bCol + ldRow) * K + kb + ldC0 * 8;
        asm volatile("cp.async.cg.shared.global [%0], [%1], 16;"
                     :: "r"(aDst + stOff), "l"(aSrc) : "memory");
        asm volatile("cp.async.cg.shared.global [%0], [%1], 16;"
                     :: "r"(aDst + stOff + 16), "l"(aSrc + 8) : "memory");
        asm volatile("cp.async.cg.shared.global [%0], [%1], 16;"
                     :: "r"(bDst + stOff), "l"(bSrc) : "memory");
        asm volatile("cp.async.cg.shared.global [%0], [%1], 16;"
                     :: "r"(bDst + stOff + 16), "l"(bSrc + 8) : "memory");
    };

    float acc[2][8][4];
    #pragma unroll
    for (int i = 0; i < 2; ++i)
        #pragma unroll
        for (int j = 0; j < 8; ++j)
            #pragma unroll
            for (int r = 0; r < 4; ++r) acc[i][j][r] = 0.0f;

    // Prologue: fill 4 stages
    #pragma unroll
    for (int s = 0; s < STAGES - 1; ++s) {
        load_tile(s, aBase + s * TILE_B, bBase + s * TILE_B);
        asm volatile("cp.async.commit_group;" ::: "memory");
    }

    uint32_t rdA = aBase, rdB = bBase;
    uint32_t wrA = aBase + (STAGES - 1) * TILE_B;
    uint32_t wrB = bBase + (STAGES - 1) * TILE_B;

    for (int kt = 0; kt < KT; ++kt) {
        asm volatile("cp.async.wait_group %0;" :: "n"(STAGES - 2) : "memory");
        __syncthreads();
        if (kt + STAGES - 1 < KT) load_tile(kt + STAGES - 1, wrA, wrB);
        asm volatile("cp.async.commit_group;" ::: "memory");
        wrA += TILE_B; if (wrA == aEnd) wrA = aBase;
        wrB += TILE_B; if (wrB == bEnd) wrB = bBase;

        // ---- fragment pipeline: ks=0 loads, ks=16 A loads, MMA ks0,
        //      ks=16 B loads, MMA ks16 ----
        uint32_t a0[2][4], a1[2][4], b0[4][4], b1[4][4];
        LDSM_X4(a0[0], rdA + aOff0);
        LDSM_X4(a0[1], rdA + aOff1);
        LDSM_X4(b0[0], rdB + bOff[0]);
        LDSM_X4(b0[1], rdB + bOff[1]);
        LDSM_X4(b0[2], rdB + bOff[2]);
        LDSM_X4(b0[3], rdB + bOff[3]);
        LDSM_X4(a1[0], rdA + aOff0 + 32);
        LDSM_X4(a1[1], rdA + aOff1 + 32);

        #pragma unroll
        for (int mf = 0; mf < 2; ++mf)
            #pragma unroll
            for (int g = 0; g < 4; ++g) {
                MMA_16816(acc[mf][2 * g],     a0[mf], b0[g][0], b0[g][2]);
                MMA_16816(acc[mf][2 * g + 1], a0[mf], b0[g][1], b0[g][3]);
            }

        LDSM_X4(b1[0], rdB + bOff[0] + 32);
        LDSM_X4(b1[1], rdB + bOff[1] + 32);
        LDSM_X4(b1[2], rdB + bOff[2] + 32);
        LDSM_X4(b1[3], rdB + bOff[3] + 32);

        #pragma unroll
        for (int mf = 0; mf < 2; ++mf)
            #pragma unroll
            for (int g = 0; g < 4; ++g) {
                MMA_16816(acc[mf][2 * g],     a1[mf], b1[g][0], b1[g][2]);
                MMA_16816(acc[mf][2 * g + 1], a1[mf], b1[g][1], b1[g][3]);
            }

        rdA += TILE_B; if (rdA == aEnd) rdA = aBase;
        rdB += TILE_B; if (rdB == bEnd) rdB = bBase;
    }

    if (MODE == 0) {
        // Fused gate epilogue (identical to R8).
        const int q    = lane >> 2;
        const bool odd = (q & 1) != 0;
        const int cB   = bCol + wn * 64 + (lane & 3) * 2;
        #pragma unroll
        for (int nf = 0; nf < 8; ++nf) {
            const int c = cB + nf * 8;
            const float2 b2v = *(const float2*)&aux[c];
            #pragma unroll
            for (int mf = 0; mf < 2; ++mf) {
                #pragma unroll
                for (int half = 0; half < 2; ++half) {
                    float x = acc[mf][nf][half * 2 + 0];
                    float y = acc[mf][nf][half * 2 + 1];
                    int fl = ((x + b2v.x) > 0.0f ? 1 : 0) |
                             ((y + b2v.y) > 0.0f ? 2 : 0);
                    int pf = __shfl_xor_sync(0xFFFFFFFFu, fl, 4);
                    if (odd) {
                        int r = bRow + wm * 32 + mf * 16 + half * 8 + q;
                        int tb = r >> 1;
                        float tx = (pf & 1) ? x : 0.0f;
                        float ty = (pf & 2) ? y : 0.0f;
                        __nv_bfloat16 hx, lx, hy, ly;
                        split_bf16(tx, hx, lx);
                        split_bf16(ty, hy, ly);
                        __nv_bfloat162 h2; h2.x = hx; h2.y = hy;
                        __nv_bfloat162 l2; l2.x = lx; l2.y = ly;
                        *(__nv_bfloat162*)&g_T2hi[(size_t)tb * H2 + c] = h2;
                        *(__nv_bfloat162*)&g_T2lo[(size_t)tb * H2 + c] = l2;
                    }
                }
            }
        }
    } else {
        // Fused sum-of-squares epilogue (identical to R8).
        float s = 0.0f;
        #pragma unroll
        for (int mf = 0; mf < 2; ++mf)
            #pragma unroll
            for (int nf = 0; nf < 8; ++nf)
                #pragma unroll
                for (int r = 0; r < 4; ++r) {
                    float v = acc[mf][nf][r];
                    s = fmaf(v, v, s);
                }
        #pragma unroll
        for (int o = 16; o > 0; o >>= 1)
            s += __shfl_xor_sync(0xFFFFFFFFu, s, o);
        __syncthreads();
        float* red = (float*)sm;
        if (lane == 0) red[wid] = s;
        __syncthreads();
        if (tid == 0) {
            float tot = 0.0f;
            #pragma unroll
            for (int w = 0; w < 8; ++w) tot += red[w];
            g_part[blockIdx.y * gridDim.x + blockIdx.x] = tot;
        }
    }
}

// ---------------------------------------------------------------------------
// Final deterministic sum over n partials.
// ---------------------------------------------------------------------------
__global__ void k_finalize(float* __restrict__ out, int n) {
    __shared__ float red[256];
    float s = 0.0f;
    for (int i = threadIdx.x; i < n; i += 256) s += g_part[i];
    red[threadIdx.x] = s;
    __syncthreads();
    for (int o = 128; o > 0; o >>= 1) {
        if (threadIdx.x < o) red[threadIdx.x] += red[threadIdx.x + o];
        __syncthreads();
    }
    if (threadIdx.x == 0) out[0] = red[0];
}

// ---------------------------------------------------------------------------
// Launch.  Inputs: 0:c0 1:c1 2:interior 3:W1 4:b1 5:W2 6:b2 7:W3 8:b3(unused)
// ---------------------------------------------------------------------------
extern "C" void kernel_launch(void* const* d_in, const int* in_sizes, int n_in,
                              void* d_out, int out_size) {
    const float* c0       = (const float*)d_in[0];
    const float* c1       = (const float*)d_in[1];
    const float* interior = (const float*)d_in[2];
    const float* W1       = (const float*)d_in[3];
    const float* b1       = (const float*)d_in[4];
    const float* W2       = (const float*)d_in[5];
    const float* b2       = (const float*)d_in[6];
    const float* W3       = (const float*)d_in[7];
    (void)in_sizes; (void)n_in; (void)out_size;

    __nv_bfloat16 *X1hi, *X1lo, *W2thi, *W2tlo, *W3thi, *W3tlo, *T2hi, *T2lo;
    cudaGetSymbolAddress((void**)&X1hi,  g_X1hi);
    cudaGetSymbolAddress((void**)&X1lo,  g_X1lo);
    cudaGetSymbolAddress((void**)&W2thi, g_W2thi);
    cudaGetSymbolAddress((void**)&W2tlo, g_W2tlo);
    cudaGetSymbolAddress((void**)&W3thi, g_W3thi);
    cudaGetSymbolAddress((void**)&W3tlo, g_W3tlo);
    cudaGetSymbolAddress((void**)&T2hi,  g_T2hi);
    cudaGetSymbolAddress((void**)&T2lo,  g_T2lo);

    cudaFuncSetAttribute(k_mma_gemm<0>,
                         cudaFuncAttributeMaxDynamicSharedMemorySize, SMEM_BYTES);
    cudaFuncSetAttribute(k_mma_gemm<1>,
                         cudaFuncAttributeMaxDynamicSharedMemorySize, SMEM_BYTES);

    // Weight transpose+split
    k_transpose_split<<<dim3(H2 / 32, H1 / 32), dim3(32, 8)>>>(W2, W2thi, W2tlo, H1, H2);
    k_transpose_split<<<dim3(DD / 32, H2 / 32), dim3(32, 8)>>>(W3, W3thi, W3tlo, H2, DD);

    // L1 forward + tangent (interleaved rows, pads zeroed in-kernel)
    k_layer1<<<1024, 256>>>(c0, c1, interior, W1, b1);

    // GEMM1 + fused gate: X1(2048x512) @ W2t -> t2 bf16 splits
    k_mma_gemm<0><<<dim3(H2 / BN, X1_ROWS / BM), 256, SMEM_BYTES>>>(
        X1hi, X1lo, W2thi, W2tlo, b2, H1, H2, 3 * H1 / BK);

    // GEMM2 + fused sqsum: t2(1024x2048) @ W3t -> per-CTA partials
    const int g2x = DD / BN, g2y = T2_ROWS / BM;   // 24 x 8 = 192
    k_mma_gemm<1><<<dim3(g2x, g2y), 256, SMEM_BYTES>>>(
        T2hi, T2lo, W3thi, W3tlo, nullptr, H2, DD, 3 * H2 / BK);

    // energy = sum of partials (fixed order)
    k_finalize<<<1, 256>>>((float*)d_out, g2x * g2y);
}